// round 16
// baseline (speedup 1.0000x reference)
#include <cuda_runtime.h>
#include <cuda_bf16.h>
#include <math.h>
#include <stdint.h>

// ---------------------------------------------------------------------------
// FusedGatedDeltaNet: B=1, S=1024, D_IN=2048, H_QK=8, H_V=16, DK=DV=128,
// KCONV=4, FUSED=4096, D_OUT=1024, D_OUT_VG=2048
// R16 = R15 (best) + w_out split hidden in the scan+gate window + wider rms.
// ---------------------------------------------------------------------------

#define SEQ    1024
#define DIN    2048
#define FUSEDC 4096
#define HV     16
#define HQK    8
#define DOVG   2048
#define GK     2048

// ------------------------- scratch (static, no alloc) ----------------------
__device__ float g_qkv_pre[SEQ * FUSEDC];
__device__ float g_qkv[SEQ * FUSEDC];
__device__ float g_gate[SEQ * DOVG];
__device__ float g_ctx[SEQ * DOVG];
__device__ float g_beta[HV * SEQ];
__device__ float g_alpha[HV * SEQ];
__device__ float g_pp[HQK * (SEQ / 2) * 4];

__device__ __nv_bfloat16 g_x_hi[SEQ * DIN],       g_x_lo[SEQ * DIN];
__device__ __nv_bfloat16 g_wqkv_hi[FUSEDC * DIN], g_wqkv_lo[FUSEDC * DIN];
__device__ __nv_bfloat16 g_wg_hi[DOVG * DIN],     g_wg_lo[DOVG * DIN];
__device__ __nv_bfloat16 g_wo_hi[DOVG * DIN],     g_wo_lo[DOVG * DIN];
__device__ __nv_bfloat16 g_gctx_hi[SEQ * DOVG],   g_gctx_lo[SEQ * DOVG];
__device__ __nv_bfloat16 g_wba_hi[128 * DIN],     g_wba_lo[128 * DIN];

// ------------------------- helpers -----------------------------------------
__device__ __forceinline__ uint32_t smem_u32(const void* p) {
    uint32_t a;
    asm("{ .reg .u64 t; cvta.to.shared.u64 t, %1; cvt.u32.u64 %0, t; }"
        : "=r"(a) : "l"(p));
    return a;
}
__device__ __forceinline__ void cp_async16(uint32_t dst, const void* src) {
    asm volatile("cp.async.cg.shared.global [%0], [%1], 16;"
                 :: "r"(dst), "l"(src));
}
__device__ __forceinline__ void cp_async4(uint32_t dst, const void* src) {
    asm volatile("cp.async.ca.shared.global [%0], [%1], 4;"
                 :: "r"(dst), "l"(src));
}
__device__ __forceinline__ void cp_commit() {
    asm volatile("cp.async.commit_group;");
}
__device__ __forceinline__ void ldmatrix_x4(uint32_t* r, uint32_t addr) {
    asm volatile("ldmatrix.sync.aligned.m8n8.x4.shared.b16 {%0,%1,%2,%3}, [%4];"
                 : "=r"(r[0]), "=r"(r[1]), "=r"(r[2]), "=r"(r[3]) : "r"(addr));
}
__device__ __forceinline__ void ldmatrix_x2(uint32_t* r, uint32_t addr) {
    asm volatile("ldmatrix.sync.aligned.m8n8.x2.shared.b16 {%0,%1}, [%2];"
                 : "=r"(r[0]), "=r"(r[1]) : "r"(addr));
}
__device__ __forceinline__ void mma16816(float* d, const uint32_t* a, const uint32_t* b) {
    asm volatile("mma.sync.aligned.m16n8k16.row.col.f32.bf16.bf16.f32 "
                 "{%0,%1,%2,%3}, {%4,%5,%6,%7}, {%8,%9}, {%0,%1,%2,%3};"
                 : "+f"(d[0]), "+f"(d[1]), "+f"(d[2]), "+f"(d[3])
                 : "r"(a[0]), "r"(a[1]), "r"(a[2]), "r"(a[3]),
                   "r"(b[0]), "r"(b[1]));
}
__device__ __forceinline__ float silu(float v) { return v / (1.f + expf(-v)); }

__device__ __forceinline__ uint32_t split_pair(float a, float b,
                                               uint32_t& lo_out) {
    __nv_bfloat16 ha = __float2bfloat16(a), hb = __float2bfloat16(b);
    __nv_bfloat16 la = __float2bfloat16(a - __bfloat162float(ha));
    __nv_bfloat16 lb = __float2bfloat16(b - __bfloat162float(hb));
    __nv_bfloat162 h2 = __halves2bfloat162(ha, hb);
    __nv_bfloat162 l2 = __halves2bfloat162(la, lb);
    lo_out = *(uint32_t*)&l2;
    return *(uint32_t*)&h2;
}

// ---------------------------------------------------------------------------
// Shared GEMM tile body (3-pass hi/lo split, combined chunks), 256 threads.
// ---------------------------------------------------------------------------
#define SASTR   40
#define ARR_B   10240
#define STAGEB  (4 * ARR_B)
#define GSMEM   (2 * STAGEB)            // 81920
#define NCHT    (GK / 32)

__device__ __forceinline__ void gemm_tile(
    char* dynsmem, int tid, int bm, int bn,
    const __nv_bfloat16* __restrict__ Ahi, const __nv_bfloat16* __restrict__ Alo,
    const __nv_bfloat16* __restrict__ BH, const __nv_bfloat16* __restrict__ BL,
    float* __restrict__ Cp, int N, int epi,
    const float* __restrict__ log_A, const float* __restrict__ dt_bias,
    float* __restrict__ beta_out, float* __restrict__ alpha_out)
{
    const uint32_t sb = smem_u32(dynsmem);
    const int lane = tid & 31;
    const int wrp  = tid >> 5;
    const int wm   = wrp >> 2;
    const int wn   = wrp & 3;

    const int ld_row = tid >> 2;
    const int ld_seg = (tid & 3) * 8;
    const uint32_t st_off = (uint32_t)(ld_row * SASTR + ld_seg) * 2;

    const int a_row = wm * 64 + (lane & 15);
    const int a_ko  = (lane >> 4) * 8;
    const uint32_t aH0 = sb + (uint32_t)(a_row * SASTR + a_ko) * 2;
    const int b_row = wn * 32 + (lane & 7);
    const int b_ko  = ((lane >> 3) & 1) * 8;
    const uint32_t bH0 = sb + 2 * ARR_B + (uint32_t)(b_row * SASTR + b_ko) * 2;

    float acc[4][4][4];
#pragma unroll
    for (int i = 0; i < 4; ++i)
#pragma unroll
        for (int j = 0; j < 4; ++j)
#pragma unroll
            for (int q = 0; q < 4; ++q) acc[i][j][q] = 0.f;

#define ISSUE_CHUNK(stagebase, kc)                                             \
    do {                                                                       \
        _Pragma("unroll")                                                      \
        for (int it = 0; it < 2; ++it) {                                       \
            int row = ld_row + it * 64;                                        \
            uint32_t o = st_off + (uint32_t)(it * 64 * SASTR) * 2;             \
            size_t ga = (size_t)(bm + row) * GK + (kc) + ld_seg;               \
            size_t gb = (size_t)(bn + row) * GK + (kc) + ld_seg;               \
            cp_async16((stagebase) + o,              Ahi + ga);                \
            cp_async16((stagebase) + ARR_B + o,      Alo + ga);                \
            cp_async16((stagebase) + 2 * ARR_B + o,  BH + gb);                 \
            cp_async16((stagebase) + 3 * ARR_B + o,  BL + gb);                 \
        }                                                                      \
    } while (0)

    ISSUE_CHUNK(sb, 0);
    cp_commit();
    ISSUE_CHUNK(sb + STAGEB, 32);
    cp_commit();

    for (int c = 0; c < NCHT; ++c) {
        asm volatile("cp.async.wait_group 1;");
        __syncthreads();

        const uint32_t soff = (uint32_t)(c & 1) * STAGEB;
#pragma unroll
        for (int ks = 0; ks < 2; ++ks) {
            uint32_t ah[4][4], bh[4][2], bl[4][2];
#pragma unroll
            for (int mt = 0; mt < 4; ++mt)
                ldmatrix_x4(ah[mt], aH0 + soff + mt * (16 * SASTR * 2) + ks * 32);
#pragma unroll
            for (int nt = 0; nt < 4; ++nt)
                ldmatrix_x2(bh[nt], bH0 + soff + nt * (8 * SASTR * 2) + ks * 32);
#pragma unroll
            for (int mt = 0; mt < 4; ++mt)
#pragma unroll
                for (int nt = 0; nt < 4; ++nt)
                    mma16816(acc[mt][nt], ah[mt], bh[nt]);
#pragma unroll
            for (int nt = 0; nt < 4; ++nt)
                ldmatrix_x2(bl[nt], bH0 + ARR_B + soff + nt * (8 * SASTR * 2) + ks * 32);
#pragma unroll
            for (int mt = 0; mt < 4; ++mt)
#pragma unroll
                for (int nt = 0; nt < 4; ++nt)
                    mma16816(acc[mt][nt], ah[mt], bl[nt]);
#pragma unroll
            for (int mt = 0; mt < 4; ++mt)
                ldmatrix_x4(ah[mt], aH0 + ARR_B + soff + mt * (16 * SASTR * 2) + ks * 32);
#pragma unroll
            for (int mt = 0; mt < 4; ++mt)
#pragma unroll
                for (int nt = 0; nt < 4; ++nt)
                    mma16816(acc[mt][nt], ah[mt], bh[nt]);
        }
        __syncthreads();

        if (c + 2 < NCHT) {
            const uint32_t so = sb + (uint32_t)(c & 1) * STAGEB;
            ISSUE_CHUNK(so, (c + 2) * 32);
        }
        cp_commit();
    }
#undef ISSUE_CHUNK

    if (epi == 3) {
        if (wn != 0) return;
#pragma unroll
        for (int mt = 0; mt < 4; ++mt) {
            int row0 = bm + wm * 64 + mt * 16 + (lane >> 2);
#pragma unroll
            for (int nt = 0; nt < 4; ++nt) {
#pragma unroll
                for (int half = 0; half < 2; ++half) {
#pragma unroll
                    for (int e = 0; e < 2; ++e) {
                        int col = nt * 8 + (lane & 3) * 2 + e;
                        int t = row0 + half * 8;
                        float v = acc[mt][nt][half * 2 + e];
                        if (col < 16) {
                            beta_out[col * SEQ + t] = 1.f / (1.f + expf(-v));
                        } else {
                            int h = col - 16;
                            float z = v + dt_bias[h];
                            float sp = (z > 20.f) ? z : log1pf(expf(z));
                            alpha_out[h * SEQ + t] = expf(-expf(log_A[h]) * sp);
                        }
                    }
                }
            }
        }
        return;
    }
#pragma unroll
    for (int mt = 0; mt < 4; ++mt) {
        int row0 = bm + wm * 64 + mt * 16 + (lane >> 2);
#pragma unroll
        for (int nt = 0; nt < 4; ++nt) {
            int col = bn + wn * 32 + nt * 8 + (lane & 3) * 2;
            float2 v0 = make_float2(acc[mt][nt][0], acc[mt][nt][1]);
            float2 v1 = make_float2(acc[mt][nt][2], acc[mt][nt][3]);
            if (epi == 1) {
                v0.x = silu(v0.x); v0.y = silu(v0.y);
                v1.x = silu(v1.x); v1.y = silu(v1.y);
            }
            *(float2*)(Cp + (size_t)row0 * N + col) = v0;
            *(float2*)(Cp + (size_t)(row0 + 8) * N + col) = v1;
        }
    }
}

// ---------------------------------------------------------------------------
// gemm3c kernel wrapper (column-segmented)
// ---------------------------------------------------------------------------
__global__ void __launch_bounds__(256, 2) gemm3c(
    const __nv_bfloat16* __restrict__ Ahi, const __nv_bfloat16* __restrict__ Alo,
    const __nv_bfloat16* __restrict__ B1h, const __nv_bfloat16* __restrict__ B1l,
    float* __restrict__ C1, int N1, int epi1,
    const __nv_bfloat16* __restrict__ B3h, const __nv_bfloat16* __restrict__ B3l,
    const float* __restrict__ log_A, const float* __restrict__ dt_bias,
    float* __restrict__ beta_out, float* __restrict__ alpha_out)
{
    extern __shared__ char dynsmem[];
    const int bm = blockIdx.y * 128;
    int gx = blockIdx.x * 128;
    if (gx < N1) {
        gemm_tile(dynsmem, threadIdx.x, bm, gx, Ahi, Alo, B1h, B1l,
                  C1, N1, epi1, log_A, dt_bias, beta_out, alpha_out);
    } else {
        gemm_tile(dynsmem, threadIdx.x, bm, 0, Ahi, Alo, B3h, B3l,
                  (float*)0, 0, 3, log_A, dt_bias, beta_out, alpha_out);
    }
}

// ---------------------------------------------------------------------------
// Fused conv kernel, ONE launch. grid (SEQ/4, 16), 256 threads.
// blk < 8:  q/k head pair: conv+silu+l2norm + pair scalars
// blk >= 8: v channels, plain conv+silu
// ---------------------------------------------------------------------------
__global__ void __launch_bounds__(256) conv_all_kernel(
    const float* __restrict__ in, const float* __restrict__ w,
    float* __restrict__ out, float* __restrict__ pp)
{
    const int t0   = blockIdx.x * 4;
    const int blk  = blockIdx.y;
    const int tid  = threadIdx.x;
    const int lane = tid & 31;
    const int wrp  = tid >> 5;

    if (blk >= 8) {
        const int c = 2048 + (blk - 8) * 256 + tid;
        float4 wc = *(const float4*)(w + c * 4);
        const float* col = in + c;
        float p1 = (t0 >= 1) ? col[(size_t)(t0 - 1) * FUSEDC] : 0.f;
        float p2 = (t0 >= 2) ? col[(size_t)(t0 - 2) * FUSEDC] : 0.f;
        float p3 = (t0 >= 3) ? col[(size_t)(t0 - 3) * FUSEDC] : 0.f;
        float c0 = col[(size_t)(t0 + 0) * FUSEDC];
        float c1 = col[(size_t)(t0 + 1) * FUSEDC];
        float c2 = col[(size_t)(t0 + 2) * FUSEDC];
        float c3 = col[(size_t)(t0 + 3) * FUSEDC];
        out[(size_t)(t0 + 0) * FUSEDC + c] = silu(wc.w * c0 + wc.z * p1 + wc.y * p2 + wc.x * p3);
        out[(size_t)(t0 + 1) * FUSEDC + c] = silu(wc.w * c1 + wc.z * c0 + wc.y * p1 + wc.x * p2);
        out[(size_t)(t0 + 2) * FUSEDC + c] = silu(wc.w * c2 + wc.z * c1 + wc.y * c0 + wc.x * p1);
        out[(size_t)(t0 + 3) * FUSEDC + c] = silu(wc.w * c3 + wc.z * c2 + wc.y * c1 + wc.x * c0);
        return;
    }

    const int hq   = blk;
    const int half = tid >> 7;
    const int d    = tid & 127;
    const int c    = half * 1024 + hq * 128 + d;

    float4 wc = *(const float4*)(w + c * 4);
    const float* col = in + c;

    float p1 = (t0 >= 1) ? col[(size_t)(t0 - 1) * FUSEDC] : 0.f;
    float p2 = (t0 >= 2) ? col[(size_t)(t0 - 2) * FUSEDC] : 0.f;
    float p3 = (t0 >= 3) ? col[(size_t)(t0 - 3) * FUSEDC] : 0.f;
    float c0 = col[(size_t)(t0 + 0) * FUSEDC];
    float c1 = col[(size_t)(t0 + 1) * FUSEDC];
    float c2 = col[(size_t)(t0 + 2) * FUSEDC];
    float c3 = col[(size_t)(t0 + 3) * FUSEDC];

    float v[4];
    v[0] = silu(wc.w * c0 + wc.z * p1 + wc.y * p2 + wc.x * p3);
    v[1] = silu(wc.w * c1 + wc.z * c0 + wc.y * p1 + wc.x * p2);
    v[2] = silu(wc.w * c2 + wc.z * c1 + wc.y * c0 + wc.x * p1);
    v[3] = silu(wc.w * c3 + wc.z * c2 + wc.y * c1 + wc.x * c0);

    __shared__ float sred[8][128];
    __shared__ float sscale[8];
#pragma unroll
    for (int i = 0; i < 4; ++i) sred[half * 4 + i][d] = v[i] * v[i];
    __syncthreads();
    {
        float s = sred[wrp][lane] + sred[wrp][lane + 32] +
                  sred[wrp][lane + 64] + sred[wrp][lane + 96];
#pragma unroll
        for (int m = 16; m; m >>= 1) s += __shfl_xor_sync(0xffffffffu, s, m);
        if (lane == 0) {
            float sc = rsqrtf(s + 1e-6f);
            if (wrp < 4) sc *= 0.08838834764831845f;
            sscale[wrp] = sc;
        }
    }
    __syncthreads();
#pragma unroll
    for (int i = 0; i < 4; ++i) v[i] *= sscale[half * 4 + i];
#pragma unroll
    for (int i = 0; i < 4; ++i)
        out[(size_t)(t0 + i) * FUSEDC + c] = v[i];

    __shared__ float sqk[8][128];
#pragma unroll
    for (int i = 0; i < 4; ++i) sqk[half * 4 + i][d] = v[i];
    __syncthreads();

    float q0 = sqk[0][d], q1 = sqk[1][d], q2 = sqk[2][d], q3 = sqk[3][d];
    float k0 = sqk[4][d], k1 = sqk[5][d], k2 = sqk[6][d], k3 = sqk[7][d];
    float pv[8] = { k1 * k0, q0 * k0, q1 * k0, q1 * k1,
                    k3 * k2, q2 * k2, q3 * k2, q3 * k3 };
#pragma unroll
    for (int m = 16; m; m >>= 1) {
#pragma unroll
        for (int i = 0; i < 8; ++i)
            pv[i] += __shfl_xor_sync(0xffffffffu, pv[i], m);
    }
    __shared__ float swv[4][8];
    if (wrp < 4 && lane == 0) {
#pragma unroll
        for (int i = 0; i < 8; ++i) swv[wrp][i] = pv[i];
    }
    __syncthreads();
    if (tid < 8) {
        float s = swv[0][tid] + swv[1][tid] + swv[2][tid] + swv[3][tid];
        int p = tid >> 2, i = tid & 3;
        pp[(size_t)hq * (SEQ / 2) * 4 + ((t0 >> 1) + p) * 4 + i] = s;
    }
}

// ---------------------------------------------------------------------------
// Merged kernel, 320 blocks:
//  [0,128)    scan (16 heads x 8 col-blocks of 16 cols), 2-step + pair scalars
//  [128,256)  gate GEMM tiles (silu epilogue)
//  [256,320)  w_out fp32 -> bf16 hi/lo split (hidden in this window)
// Scan smem/buf (floats): q 4096 | k 4096 | v 512 | b 32 | a 32 | pp 64 = 8832
// ---------------------------------------------------------------------------
#define TSCHUNK 32
#define SC_K   4096
#define SC_V   8192
#define SC_B   8704
#define SC_A   8736
#define SC_P   8768
#define SCAN_BUF_F 8832
#define N4_WO_SEG (DOVG * DIN / 4)      // float4 count of w_out

__global__ void __launch_bounds__(256, 2) scan_gate_kernel(
    const float* __restrict__ qkv, const float* __restrict__ beta,
    const float* __restrict__ alpha, const float* __restrict__ pp,
    float* __restrict__ ctx,
    const __nv_bfloat16* __restrict__ x_hi, const __nv_bfloat16* __restrict__ x_lo,
    const __nv_bfloat16* __restrict__ wg_hi, const __nv_bfloat16* __restrict__ wg_lo,
    float* __restrict__ gate,
    const float* __restrict__ wo, __nv_bfloat16* __restrict__ wo_hi,
    __nv_bfloat16* __restrict__ wo_lo)
{
    extern __shared__ char dynsmem[];
    const int bx  = blockIdx.x;
    const int tid = threadIdx.x;

    if (bx >= 256) {
        // ---- w_out split (consumed only by the final GEMM) ----
        const int ci = bx - 256;                       // 0..63
        // 64 CTAs x 256 threads x 64 float4 pairs -> process 2 float4/iter
        int base = ci * (N4_WO_SEG / 64);              // 16384 float4 per CTA
#pragma unroll 1
        for (int g = 0; g < (N4_WO_SEG / 64) / 512; ++g) {   // 32 iters
            int i = base + (g * 256 + tid) * 2;
            float4 v0 = ((const float4*)wo)[i];
            float4 v1 = ((const float4*)wo)[i + 1];
            uint4 H, L;
            H.x = split_pair(v0.x, v0.y, L.x);
            H.y = split_pair(v0.z, v0.w, L.y);
            H.z = split_pair(v1.x, v1.y, L.z);
            H.w = split_pair(v1.z, v1.w, L.w);
            ((uint4*)wo_hi)[i >> 1] = H;
            ((uint4*)wo_lo)[i >> 1] = L;
        }
        return;
    }

    if (bx >= 128) {
        const int bi = bx - 128;
        const int bn = (bi & 15) * 128;
        const int bm = (bi >> 4) * 128;
        gemm_tile(dynsmem, tid, bm, bn, x_hi, x_lo, wg_hi, wg_lo,
                  gate, DOVG, 1, (const float*)0, (const float*)0,
                  (float*)0, (float*)0);
        return;
    }

    // ---- scan ----
    float* ss = (float*)dynsmem;
    const int h  = bx >> 3;
    const int cb = bx & 7;
    const int hq = h >> 1;
    const int j   = tid >> 4;
    const int sub = tid & 15;

    const uint32_t ssb = smem_u32(ss);

    const float* qbase = qkv + hq * 128;
    const float* kbase = qkv + 1024 + hq * 128;
    const float* vbase = qkv + 2048 + h * 128 + cb * 16;
    const float* bbase = beta + h * SEQ;
    const float* abase = alpha + h * SEQ;
    const float* pbase = pp + (size_t)hq * (SEQ / 2) * 4;
    float* obase = ctx + h * 128 + cb * 16 + j;

    const int c0 = sub * 2;
    const int c0s = c0 ^ (c0 >> 3);
    const int c1 = c0 + 1;
    const int c1s = c1 ^ (c1 >> 3);

#define SCAN_ISSUE(buf, t0)                                                    \
    do {                                                                       \
        uint32_t sbb = ssb + (uint32_t)(buf) * (SCAN_BUF_F * 4);               \
        _Pragma("unroll")                                                      \
        for (int u = 0; u < 4; ++u) {                                          \
            int lin = tid + u * 256;                                           \
            int tt = lin >> 5, d4 = lin & 31;                                  \
            int sw = d4 ^ (d4 >> 3);                                           \
            size_t goff = (size_t)((t0) + tt) * FUSEDC + d4 * 4;               \
            uint32_t so = (uint32_t)(tt * 32 + sw) * 16;                       \
            cp_async16(sbb + so, qbase + goff);                                \
            cp_async16(sbb + SC_K * 4 + so, kbase + goff);                     \
        }                                                                      \
        if (tid < 128) {                                                       \
            int tt = tid >> 2, j4 = tid & 3;                                   \
            cp_async16(sbb + SC_V * 4 + (uint32_t)tid * 16,                    \
                       vbase + (size_t)((t0) + tt) * FUSEDC + j4 * 4);         \
        } else if (tid < 160) {                                                \
            cp_async4(sbb + SC_B * 4 + (uint32_t)(tid - 128) * 4,              \
                      bbase + (t0) + tid - 128);                               \
        } else if (tid < 192) {                                                \
            cp_async4(sbb + SC_A * 4 + (uint32_t)(tid - 160) * 4,              \
                      abase + (t0) + tid - 160);                               \
        } else if (tid < 208) {                                                \
            cp_async16(sbb + SC_P * 4 + (uint32_t)(tid - 192) * 16,            \
                       pbase + ((t0) >> 1) * 4 + (tid - 192) * 4);             \
        }                                                                      \
        cp_commit();                                                           \
    } while (0)

    float S[8];
#pragma unroll
    for (int i = 0; i < 8; ++i) S[i] = 0.f;

    SCAN_ISSUE(0, 0);

    for (int ci = 0; ci < SEQ / TSCHUNK; ++ci) {
        asm volatile("cp.async.wait_group 0;");
        __syncthreads();
        if (ci + 1 < SEQ / TSCHUNK) SCAN_ISSUE((ci + 1) & 1, (ci + 1) * TSCHUNK);

        const float* sqf = ss + (ci & 1) * SCAN_BUF_F;
        const float* skf = sqf + SC_K;
        const float* svf = sqf + SC_V;
        const float* sbf = sqf + SC_B;
        const float* saf = sqf + SC_A;
        const float* spf = sqf + SC_P;
        const int t0 = ci * TSCHUNK;

#pragma unroll 2
        for (int tt = 0; tt < TSCHUNK; tt += 2) {
            float a0 = saf[tt],     b0 = sbf[tt];
            float a1 = saf[tt + 1], b1 = sbf[tt + 1];
            float v0 = svf[tt * 16 + j];
            float v1 = svf[(tt + 1) * 16 + j];
            const int tp = tt >> 1;
            float ckk   = spf[tp * 4 + 0];
            float cqk   = spf[tp * 4 + 1];
            float cq1k  = spf[tp * 4 + 2];
            float cq1k1 = spf[tp * 4 + 3];

            float kr0[8], qr0[8], kr1[8], qr1[8];
            *(float4*)(kr0)     = *(const float4*)&skf[tt * 128 + c0s * 4];
            *(float4*)(kr0 + 4) = *(const float4*)&skf[tt * 128 + c1s * 4];
            *(float4*)(qr0)     = *(const float4*)&sqf[tt * 128 + c0s * 4];
            *(float4*)(qr0 + 4) = *(const float4*)&sqf[tt * 128 + c1s * 4];
            *(float4*)(kr1)     = *(const float4*)&skf[(tt + 1) * 128 + c0s * 4];
            *(float4*)(kr1 + 4) = *(const float4*)&skf[(tt + 1) * 128 + c1s * 4];
            *(float4*)(qr1)     = *(const float4*)&sqf[(tt + 1) * 128 + c0s * 4];
            *(float4*)(qr1 + 4) = *(const float4*)&sqf[(tt + 1) * 128 + c1s * 4];

            float p = 0.f, r = 0.f, s = 0.f, w = 0.f;
#pragma unroll
            for (int i = 0; i < 8; ++i) {
                p = fmaf(kr0[i], S[i], p);
                r = fmaf(kr1[i], S[i], r);
                s = fmaf(qr0[i], S[i], s);
                w = fmaf(qr1[i], S[i], w);
            }
#pragma unroll
            for (int m = 1; m <= 8; m <<= 1) {
                p += __shfl_xor_sync(0xffffffffu, p, m);
                r += __shfl_xor_sync(0xffffffffu, r, m);
                s += __shfl_xor_sync(0xffffffffu, s, m);
                w += __shfl_xor_sync(0xffffffffu, w, m);
            }

            float u0  = b0 * fmaf(-a0, p, v0);
            float kv1 = a1 * fmaf(ckk, u0, a0 * r);
            float u1  = b1 * (v1 - kv1);
            float o0  = fmaf(cqk, u0, a0 * s);
            float aa  = a1 * a0;
            float o1  = fmaf(cq1k1, u1, fmaf(a1 * cq1k, u0, aa * w));
            float c0u = a1 * u0;

#pragma unroll
            for (int i = 0; i < 8; ++i)
                S[i] = fmaf(aa, S[i], fmaf(c0u, kr0[i], u1 * kr1[i]));

            if (sub == 0) {
                obase[(size_t)(t0 + tt) * DOVG]     = o0;
                obase[(size_t)(t0 + tt + 1) * DOVG] = o1;
            }
        }
        __syncthreads();
    }
#undef SCAN_ISSUE
}

// ---------------------------------------------------------------------------
// fp32 -> (bf16 hi, lo) split for x | w_qkv | w_gate | w_beta | w_alpha
// (w_out handled inside the scan window)
// ---------------------------------------------------------------------------
#define N4_X   (SEQ * DIN / 4)
#define N4_QKV (FUSEDC * DIN / 4)
#define N4_WG  (DOVG * DIN / 4)
#define N4_WB  (16 * DIN / 4)
#define N4_WA  (16 * DIN / 4)
#define N4_TOT (N4_X + N4_QKV + N4_WG + N4_WB + N4_WA)
#define N8_TOT (N4_TOT / 2)

__global__ void __launch_bounds__(256) split_all(
    const float* __restrict__ x, const float* __restrict__ wqkv,
    const float* __restrict__ wg,
    const float* __restrict__ wb, const float* __restrict__ wa,
    __nv_bfloat16* xh, __nv_bfloat16* xl,
    __nv_bfloat16* qh, __nv_bfloat16* ql,
    __nv_bfloat16* gh, __nv_bfloat16* gl,
    __nv_bfloat16* bah, __nv_bfloat16* bal)
{
    int g = blockIdx.x * 256 + threadIdx.x;
    if (g >= N8_TOT) return;
    int i = g * 2;
    const float* src;
    __nv_bfloat16 *hi, *lo;
    if (i < N4_X) { src = x; hi = xh; lo = xl; }
    else if ((i -= N4_X) < N4_QKV) { src = wqkv; hi = qh; lo = ql; }
    else if ((i -= N4_QKV) < N4_WG) { src = wg; hi = gh; lo = gl; }
    else if ((i -= N4_WG) < N4_WB) { src = wb; hi = bah; lo = bal; }
    else { i -= N4_WB; src = wa; hi = bah + 16 * DIN; lo = bal + 16 * DIN; }

    float4 v0 = ((const float4*)src)[i];
    float4 v1 = ((const float4*)src)[i + 1];
    uint4 H, L;
    H.x = split_pair(v0.x, v0.y, L.x);
    H.y = split_pair(v0.z, v0.w, L.y);
    H.z = split_pair(v1.x, v1.y, L.z);
    H.w = split_pair(v1.z, v1.w, L.w);
    ((uint4*)hi)[i >> 1] = H;
    ((uint4*)lo)[i >> 1] = L;
}

// ---------------------------------------------------------------------------
// rms_norm(ctx) * rms_w * gate -> split bf16 (hi/lo); 2 heads per CTA
// grid (SEQ, HV/2), 256 threads
// ---------------------------------------------------------------------------
__global__ void __launch_bounds__(256) rms_gate_kernel(
    const float* __restrict__ ctx, const float* __restrict__ gate,
    const float* __restrict__ rms_w,
    __nv_bfloat16* __restrict__ ghi, __nv_bfloat16* __restrict__ glo)
{
    const int t = blockIdx.x;
    const int h = blockIdx.y * 2 + (threadIdx.x >> 7);   // 2 heads per CTA
    const int tid = threadIdx.x & 127;
    const int wrp = (threadIdx.x >> 5) & 3;              // warp within head
    size_t idx = (size_t)t * DOVG + h * 128 + tid;
    float v = ctx[idx];
    float ss = v * v;
#pragma unroll
    for (int m = 16; m; m >>= 1) ss += __shfl_xor_sync(0xffffffffu, ss, m);
    __shared__ float sw[2][4];
    const int hh = threadIdx.x >> 7;
    if ((threadIdx.x & 31) == 0) sw[hh][wrp] = ss;
    __syncthreads();
    float tot = sw[hh][0] + sw[hh][1] + sw[hh][2] + sw[hh][3];
    float sc = rsqrtf(tot * (1.f / 128.f) + 1e-6f);
    float r = v * sc * rms_w[tid] * gate[idx];
    __nv_bfloat16 hbf = __float2bfloat16(r);
    ghi[idx] = hbf;
    glo[idx] = __float2bfloat16(r - __bfloat162float(hbf));
}

// ---------------------------------------------------------------------------
extern "C" void kernel_launch(void* const* d_in, const int* in_sizes, int n_in,
                              void* d_out, int out_size)
{
    const float* x       = (const float*)d_in[0];
    const float* w_qkv   = (const float*)d_in[1];
    const float* w_gate  = (const float*)d_in[2];
    const float* w_beta  = (const float*)d_in[3];
    const float* w_alpha = (const float*)d_in[4];
    const float* log_A   = (const float*)d_in[5];
    const float* dt_bias = (const float*)d_in[6];
    const float* conv_w  = (const float*)d_in[7];
    const float* rms_w   = (const float*)d_in[8];
    const float* w_out   = (const float*)d_in[9];
    float* out = (float*)d_out;

    float *qkv_pre, *qkv, *gate, *ctx, *beta, *alpha, *pp;
    __nv_bfloat16 *x_hi, *x_lo, *wqkv_hi, *wqkv_lo, *wg_hi, *wg_lo,
                  *wo_hi, *wo_lo, *gctx_hi, *gctx_lo, *wba_hi, *wba_lo;
    cudaGetSymbolAddress((void**)&qkv_pre, g_qkv_pre);
    cudaGetSymbolAddress((void**)&qkv,     g_qkv);
    cudaGetSymbolAddress((void**)&gate,    g_gate);
    cudaGetSymbolAddress((void**)&ctx,     g_ctx);
    cudaGetSymbolAddress((void**)&beta,    g_beta);
    cudaGetSymbolAddress((void**)&alpha,   g_alpha);
    cudaGetSymbolAddress((void**)&pp,      g_pp);
    cudaGetSymbolAddress((void**)&x_hi,    g_x_hi);
    cudaGetSymbolAddress((void**)&x_lo,    g_x_lo);
    cudaGetSymbolAddress((void**)&wqkv_hi, g_wqkv_hi);
    cudaGetSymbolAddress((void**)&wqkv_lo, g_wqkv_lo);
    cudaGetSymbolAddress((void**)&wg_hi,   g_wg_hi);
    cudaGetSymbolAddress((void**)&wg_lo,   g_wg_lo);
    cudaGetSymbolAddress((void**)&wo_hi,   g_wo_hi);
    cudaGetSymbolAddress((void**)&wo_lo,   g_wo_lo);
    cudaGetSymbolAddress((void**)&gctx_hi, g_gctx_hi);
    cudaGetSymbolAddress((void**)&gctx_lo, g_gctx_lo);
    cudaGetSymbolAddress((void**)&wba_hi,  g_wba_hi);
    cudaGetSymbolAddress((void**)&wba_lo,  g_wba_lo);

    cudaFuncSetAttribute(gemm3c, cudaFuncAttributeMaxDynamicSharedMemorySize, GSMEM);
    cudaFuncSetAttribute(scan_gate_kernel, cudaFuncAttributeMaxDynamicSharedMemorySize, GSMEM);

    // 0) precision splits (x, w_qkv, w_gate, w_beta/alpha)
    split_all<<<(N8_TOT + 255) / 256, 256>>>(
        x, w_qkv, w_gate, w_beta, w_alpha,
        x_hi, x_lo, wqkv_hi, wqkv_lo, wg_hi, wg_lo, wba_hi, wba_lo);

    // 1) qkv + beta/alpha projections (gate deferred to the scan window)
    gemm3c<<<dim3((FUSEDC + 128) / 128, SEQ / 128), 256, GSMEM>>>(
        x_hi, x_lo,
        wqkv_hi, wqkv_lo, qkv_pre, FUSEDC, 0,
        wba_hi, wba_lo,
        log_A, dt_bias, beta, alpha);

    // 2) conv+silu (+l2norm +pair scalars for q/k) — one launch
    conv_all_kernel<<<dim3(SEQ / 4, 16), 256>>>(qkv_pre, conv_w, qkv, pp);

    // 3) scan + gate GEMM + w_out split, all in one window
    scan_gate_kernel<<<320, 256, GSMEM>>>(qkv, beta, alpha, pp, ctx,
                                          x_hi, x_lo, wg_hi, wg_lo, gate,
                                          w_out, wo_hi, wo_lo);

    // 4) rms norm * gate -> split bf16 (2 heads per CTA)
    rms_gate_kernel<<<dim3(SEQ, HV / 2), 256>>>(ctx, gate, rms_w, gctx_hi, gctx_lo);

    // 5) output projection
    gemm3c<<<dim3(DOVG / 128, SEQ / 128), 256, GSMEM>>>(
        gctx_hi, gctx_lo,
        wo_hi, wo_lo, out, DOVG, 0,
        wba_hi, wba_lo,
        log_A, dt_bias, (float*)0, (float*)0);
}

// round 17
// speedup vs baseline: 1.1277x; 1.1277x over previous
#include <cuda_runtime.h>
#include <cuda_bf16.h>
#include <math.h>
#include <stdint.h>

// ---------------------------------------------------------------------------
// FusedGatedDeltaNet: B=1, S=1024, D_IN=2048, H_QK=8, H_V=16, DK=DV=128,
// KCONV=4, FUSED=4096, D_OUT=1024, D_OUT_VG=2048
// R17 = R15 (best: 256-CTA merged scan+gate window, 2-step scan + pair
// scalars, fused conv) + 2-heads-per-CTA rms_gate.
// ---------------------------------------------------------------------------

#define SEQ    1024
#define DIN    2048
#define FUSEDC 4096
#define HV     16
#define HQK    8
#define DOVG   2048
#define GK     2048

// ------------------------- scratch (static, no alloc) ----------------------
__device__ float g_qkv_pre[SEQ * FUSEDC];
__device__ float g_qkv[SEQ * FUSEDC];
__device__ float g_gate[SEQ * DOVG];
__device__ float g_ctx[SEQ * DOVG];
__device__ float g_beta[HV * SEQ];
__device__ float g_alpha[HV * SEQ];
__device__ float g_pp[HQK * (SEQ / 2) * 4];

__device__ __nv_bfloat16 g_x_hi[SEQ * DIN],       g_x_lo[SEQ * DIN];
__device__ __nv_bfloat16 g_wqkv_hi[FUSEDC * DIN], g_wqkv_lo[FUSEDC * DIN];
__device__ __nv_bfloat16 g_wg_hi[DOVG * DIN],     g_wg_lo[DOVG * DIN];
__device__ __nv_bfloat16 g_wo_hi[DOVG * DIN],     g_wo_lo[DOVG * DIN];
__device__ __nv_bfloat16 g_gctx_hi[SEQ * DOVG],   g_gctx_lo[SEQ * DOVG];
__device__ __nv_bfloat16 g_wba_hi[128 * DIN],     g_wba_lo[128 * DIN];

// ------------------------- helpers -----------------------------------------
__device__ __forceinline__ uint32_t smem_u32(const void* p) {
    uint32_t a;
    asm("{ .reg .u64 t; cvta.to.shared.u64 t, %1; cvt.u32.u64 %0, t; }"
        : "=r"(a) : "l"(p));
    return a;
}
__device__ __forceinline__ void cp_async16(uint32_t dst, const void* src) {
    asm volatile("cp.async.cg.shared.global [%0], [%1], 16;"
                 :: "r"(dst), "l"(src));
}
__device__ __forceinline__ void cp_async4(uint32_t dst, const void* src) {
    asm volatile("cp.async.ca.shared.global [%0], [%1], 4;"
                 :: "r"(dst), "l"(src));
}
__device__ __forceinline__ void cp_commit() {
    asm volatile("cp.async.commit_group;");
}
__device__ __forceinline__ void ldmatrix_x4(uint32_t* r, uint32_t addr) {
    asm volatile("ldmatrix.sync.aligned.m8n8.x4.shared.b16 {%0,%1,%2,%3}, [%4];"
                 : "=r"(r[0]), "=r"(r[1]), "=r"(r[2]), "=r"(r[3]) : "r"(addr));
}
__device__ __forceinline__ void ldmatrix_x2(uint32_t* r, uint32_t addr) {
    asm volatile("ldmatrix.sync.aligned.m8n8.x2.shared.b16 {%0,%1}, [%2];"
                 : "=r"(r[0]), "=r"(r[1]) : "r"(addr));
}
__device__ __forceinline__ void mma16816(float* d, const uint32_t* a, const uint32_t* b) {
    asm volatile("mma.sync.aligned.m16n8k16.row.col.f32.bf16.bf16.f32 "
                 "{%0,%1,%2,%3}, {%4,%5,%6,%7}, {%8,%9}, {%0,%1,%2,%3};"
                 : "+f"(d[0]), "+f"(d[1]), "+f"(d[2]), "+f"(d[3])
                 : "r"(a[0]), "r"(a[1]), "r"(a[2]), "r"(a[3]),
                   "r"(b[0]), "r"(b[1]));
}
__device__ __forceinline__ float silu(float v) { return v / (1.f + expf(-v)); }

__device__ __forceinline__ uint32_t split_pair(float a, float b,
                                               uint32_t& lo_out) {
    __nv_bfloat16 ha = __float2bfloat16(a), hb = __float2bfloat16(b);
    __nv_bfloat16 la = __float2bfloat16(a - __bfloat162float(ha));
    __nv_bfloat16 lb = __float2bfloat16(b - __bfloat162float(hb));
    __nv_bfloat162 h2 = __halves2bfloat162(ha, hb);
    __nv_bfloat162 l2 = __halves2bfloat162(la, lb);
    lo_out = *(uint32_t*)&l2;
    return *(uint32_t*)&h2;
}

// ---------------------------------------------------------------------------
// Shared GEMM tile body (3-pass hi/lo split, combined chunks), 256 threads.
// ---------------------------------------------------------------------------
#define SASTR   40
#define ARR_B   10240
#define STAGEB  (4 * ARR_B)
#define GSMEM   (2 * STAGEB)            // 81920
#define NCHT    (GK / 32)

__device__ __forceinline__ void gemm_tile(
    char* dynsmem, int tid, int bm, int bn,
    const __nv_bfloat16* __restrict__ Ahi, const __nv_bfloat16* __restrict__ Alo,
    const __nv_bfloat16* __restrict__ BH, const __nv_bfloat16* __restrict__ BL,
    float* __restrict__ Cp, int N, int epi,
    const float* __restrict__ log_A, const float* __restrict__ dt_bias,
    float* __restrict__ beta_out, float* __restrict__ alpha_out)
{
    const uint32_t sb = smem_u32(dynsmem);
    const int lane = tid & 31;
    const int wrp  = tid >> 5;
    const int wm   = wrp >> 2;
    const int wn   = wrp & 3;

    const int ld_row = tid >> 2;
    const int ld_seg = (tid & 3) * 8;
    const uint32_t st_off = (uint32_t)(ld_row * SASTR + ld_seg) * 2;

    const int a_row = wm * 64 + (lane & 15);
    const int a_ko  = (lane >> 4) * 8;
    const uint32_t aH0 = sb + (uint32_t)(a_row * SASTR + a_ko) * 2;
    const int b_row = wn * 32 + (lane & 7);
    const int b_ko  = ((lane >> 3) & 1) * 8;
    const uint32_t bH0 = sb + 2 * ARR_B + (uint32_t)(b_row * SASTR + b_ko) * 2;

    float acc[4][4][4];
#pragma unroll
    for (int i = 0; i < 4; ++i)
#pragma unroll
        for (int j = 0; j < 4; ++j)
#pragma unroll
            for (int q = 0; q < 4; ++q) acc[i][j][q] = 0.f;

#define ISSUE_CHUNK(stagebase, kc)                                             \
    do {                                                                       \
        _Pragma("unroll")                                                      \
        for (int it = 0; it < 2; ++it) {                                       \
            int row = ld_row + it * 64;                                        \
            uint32_t o = st_off + (uint32_t)(it * 64 * SASTR) * 2;             \
            size_t ga = (size_t)(bm + row) * GK + (kc) + ld_seg;               \
            size_t gb = (size_t)(bn + row) * GK + (kc) + ld_seg;               \
            cp_async16((stagebase) + o,              Ahi + ga);                \
            cp_async16((stagebase) + ARR_B + o,      Alo + ga);                \
            cp_async16((stagebase) + 2 * ARR_B + o,  BH + gb);                 \
            cp_async16((stagebase) + 3 * ARR_B + o,  BL + gb);                 \
        }                                                                      \
    } while (0)

    ISSUE_CHUNK(sb, 0);
    cp_commit();
    ISSUE_CHUNK(sb + STAGEB, 32);
    cp_commit();

    for (int c = 0; c < NCHT; ++c) {
        asm volatile("cp.async.wait_group 1;");
        __syncthreads();

        const uint32_t soff = (uint32_t)(c & 1) * STAGEB;
#pragma unroll
        for (int ks = 0; ks < 2; ++ks) {
            uint32_t ah[4][4], bh[4][2], bl[4][2];
#pragma unroll
            for (int mt = 0; mt < 4; ++mt)
                ldmatrix_x4(ah[mt], aH0 + soff + mt * (16 * SASTR * 2) + ks * 32);
#pragma unroll
            for (int nt = 0; nt < 4; ++nt)
                ldmatrix_x2(bh[nt], bH0 + soff + nt * (8 * SASTR * 2) + ks * 32);
#pragma unroll
            for (int mt = 0; mt < 4; ++mt)
#pragma unroll
                for (int nt = 0; nt < 4; ++nt)
                    mma16816(acc[mt][nt], ah[mt], bh[nt]);
#pragma unroll
            for (int nt = 0; nt < 4; ++nt)
                ldmatrix_x2(bl[nt], bH0 + ARR_B + soff + nt * (8 * SASTR * 2) + ks * 32);
#pragma unroll
            for (int mt = 0; mt < 4; ++mt)
#pragma unroll
                for (int nt = 0; nt < 4; ++nt)
                    mma16816(acc[mt][nt], ah[mt], bl[nt]);
#pragma unroll
            for (int mt = 0; mt < 4; ++mt)
                ldmatrix_x4(ah[mt], aH0 + ARR_B + soff + mt * (16 * SASTR * 2) + ks * 32);
#pragma unroll
            for (int mt = 0; mt < 4; ++mt)
#pragma unroll
                for (int nt = 0; nt < 4; ++nt)
                    mma16816(acc[mt][nt], ah[mt], bh[nt]);
        }
        __syncthreads();

        if (c + 2 < NCHT) {
            const uint32_t so = sb + (uint32_t)(c & 1) * STAGEB;
            ISSUE_CHUNK(so, (c + 2) * 32);
        }
        cp_commit();
    }
#undef ISSUE_CHUNK

    if (epi == 3) {
        if (wn != 0) return;
#pragma unroll
        for (int mt = 0; mt < 4; ++mt) {
            int row0 = bm + wm * 64 + mt * 16 + (lane >> 2);
#pragma unroll
            for (int nt = 0; nt < 4; ++nt) {
#pragma unroll
                for (int half = 0; half < 2; ++half) {
#pragma unroll
                    for (int e = 0; e < 2; ++e) {
                        int col = nt * 8 + (lane & 3) * 2 + e;
                        int t = row0 + half * 8;
                        float v = acc[mt][nt][half * 2 + e];
                        if (col < 16) {
                            beta_out[col * SEQ + t] = 1.f / (1.f + expf(-v));
                        } else {
                            int h = col - 16;
                            float z = v + dt_bias[h];
                            float sp = (z > 20.f) ? z : log1pf(expf(z));
                            alpha_out[h * SEQ + t] = expf(-expf(log_A[h]) * sp);
                        }
                    }
                }
            }
        }
        return;
    }
#pragma unroll
    for (int mt = 0; mt < 4; ++mt) {
        int row0 = bm + wm * 64 + mt * 16 + (lane >> 2);
#pragma unroll
        for (int nt = 0; nt < 4; ++nt) {
            int col = bn + wn * 32 + nt * 8 + (lane & 3) * 2;
            float2 v0 = make_float2(acc[mt][nt][0], acc[mt][nt][1]);
            float2 v1 = make_float2(acc[mt][nt][2], acc[mt][nt][3]);
            if (epi == 1) {
                v0.x = silu(v0.x); v0.y = silu(v0.y);
                v1.x = silu(v1.x); v1.y = silu(v1.y);
            }
            *(float2*)(Cp + (size_t)row0 * N + col) = v0;
            *(float2*)(Cp + (size_t)(row0 + 8) * N + col) = v1;
        }
    }
}

// ---------------------------------------------------------------------------
// gemm3c kernel wrapper (column-segmented)
// ---------------------------------------------------------------------------
__global__ void __launch_bounds__(256, 2) gemm3c(
    const __nv_bfloat16* __restrict__ Ahi, const __nv_bfloat16* __restrict__ Alo,
    const __nv_bfloat16* __restrict__ B1h, const __nv_bfloat16* __restrict__ B1l,
    float* __restrict__ C1, int N1, int epi1,
    const __nv_bfloat16* __restrict__ B3h, const __nv_bfloat16* __restrict__ B3l,
    const float* __restrict__ log_A, const float* __restrict__ dt_bias,
    float* __restrict__ beta_out, float* __restrict__ alpha_out)
{
    extern __shared__ char dynsmem[];
    const int bm = blockIdx.y * 128;
    int gx = blockIdx.x * 128;
    if (gx < N1) {
        gemm_tile(dynsmem, threadIdx.x, bm, gx, Ahi, Alo, B1h, B1l,
                  C1, N1, epi1, log_A, dt_bias, beta_out, alpha_out);
    } else {
        gemm_tile(dynsmem, threadIdx.x, bm, 0, Ahi, Alo, B3h, B3l,
                  (float*)0, 0, 3, log_A, dt_bias, beta_out, alpha_out);
    }
}

// ---------------------------------------------------------------------------
// Fused conv kernel, ONE launch. grid (SEQ/4, 16), 256 threads.
// blk < 8:  q/k head pair: conv+silu+l2norm + pair scalars
// blk >= 8: v channels, plain conv+silu
// ---------------------------------------------------------------------------
__global__ void __launch_bounds__(256) conv_all_kernel(
    const float* __restrict__ in, const float* __restrict__ w,
    float* __restrict__ out, float* __restrict__ pp)
{
    const int t0   = blockIdx.x * 4;
    const int blk  = blockIdx.y;
    const int tid  = threadIdx.x;
    const int lane = tid & 31;
    const int wrp  = tid >> 5;

    if (blk >= 8) {
        const int c = 2048 + (blk - 8) * 256 + tid;
        float4 wc = *(const float4*)(w + c * 4);
        const float* col = in + c;
        float p1 = (t0 >= 1) ? col[(size_t)(t0 - 1) * FUSEDC] : 0.f;
        float p2 = (t0 >= 2) ? col[(size_t)(t0 - 2) * FUSEDC] : 0.f;
        float p3 = (t0 >= 3) ? col[(size_t)(t0 - 3) * FUSEDC] : 0.f;
        float c0 = col[(size_t)(t0 + 0) * FUSEDC];
        float c1 = col[(size_t)(t0 + 1) * FUSEDC];
        float c2 = col[(size_t)(t0 + 2) * FUSEDC];
        float c3 = col[(size_t)(t0 + 3) * FUSEDC];
        out[(size_t)(t0 + 0) * FUSEDC + c] = silu(wc.w * c0 + wc.z * p1 + wc.y * p2 + wc.x * p3);
        out[(size_t)(t0 + 1) * FUSEDC + c] = silu(wc.w * c1 + wc.z * c0 + wc.y * p1 + wc.x * p2);
        out[(size_t)(t0 + 2) * FUSEDC + c] = silu(wc.w * c2 + wc.z * c1 + wc.y * c0 + wc.x * p1);
        out[(size_t)(t0 + 3) * FUSEDC + c] = silu(wc.w * c3 + wc.z * c2 + wc.y * c1 + wc.x * c0);
        return;
    }

    const int hq   = blk;
    const int half = tid >> 7;
    const int d    = tid & 127;
    const int c    = half * 1024 + hq * 128 + d;

    float4 wc = *(const float4*)(w + c * 4);
    const float* col = in + c;

    float p1 = (t0 >= 1) ? col[(size_t)(t0 - 1) * FUSEDC] : 0.f;
    float p2 = (t0 >= 2) ? col[(size_t)(t0 - 2) * FUSEDC] : 0.f;
    float p3 = (t0 >= 3) ? col[(size_t)(t0 - 3) * FUSEDC] : 0.f;
    float c0 = col[(size_t)(t0 + 0) * FUSEDC];
    float c1 = col[(size_t)(t0 + 1) * FUSEDC];
    float c2 = col[(size_t)(t0 + 2) * FUSEDC];
    float c3 = col[(size_t)(t0 + 3) * FUSEDC];

    float v[4];
    v[0] = silu(wc.w * c0 + wc.z * p1 + wc.y * p2 + wc.x * p3);
    v[1] = silu(wc.w * c1 + wc.z * c0 + wc.y * p1 + wc.x * p2);
    v[2] = silu(wc.w * c2 + wc.z * c1 + wc.y * c0 + wc.x * p1);
    v[3] = silu(wc.w * c3 + wc.z * c2 + wc.y * c1 + wc.x * c0);

    __shared__ float sred[8][128];
    __shared__ float sscale[8];
#pragma unroll
    for (int i = 0; i < 4; ++i) sred[half * 4 + i][d] = v[i] * v[i];
    __syncthreads();
    {
        float s = sred[wrp][lane] + sred[wrp][lane + 32] +
                  sred[wrp][lane + 64] + sred[wrp][lane + 96];
#pragma unroll
        for (int m = 16; m; m >>= 1) s += __shfl_xor_sync(0xffffffffu, s, m);
        if (lane == 0) {
            float sc = rsqrtf(s + 1e-6f);
            if (wrp < 4) sc *= 0.08838834764831845f;
            sscale[wrp] = sc;
        }
    }
    __syncthreads();
#pragma unroll
    for (int i = 0; i < 4; ++i) v[i] *= sscale[half * 4 + i];
#pragma unroll
    for (int i = 0; i < 4; ++i)
        out[(size_t)(t0 + i) * FUSEDC + c] = v[i];

    __shared__ float sqk[8][128];
#pragma unroll
    for (int i = 0; i < 4; ++i) sqk[half * 4 + i][d] = v[i];
    __syncthreads();

    float q0 = sqk[0][d], q1 = sqk[1][d], q2 = sqk[2][d], q3 = sqk[3][d];
    float k0 = sqk[4][d], k1 = sqk[5][d], k2 = sqk[6][d], k3 = sqk[7][d];
    float pv[8] = { k1 * k0, q0 * k0, q1 * k0, q1 * k1,
                    k3 * k2, q2 * k2, q3 * k2, q3 * k3 };
#pragma unroll
    for (int m = 16; m; m >>= 1) {
#pragma unroll
        for (int i = 0; i < 8; ++i)
            pv[i] += __shfl_xor_sync(0xffffffffu, pv[i], m);
    }
    __shared__ float swv[4][8];
    if (wrp < 4 && lane == 0) {
#pragma unroll
        for (int i = 0; i < 8; ++i) swv[wrp][i] = pv[i];
    }
    __syncthreads();
    if (tid < 8) {
        float s = swv[0][tid] + swv[1][tid] + swv[2][tid] + swv[3][tid];
        int p = tid >> 2, i = tid & 3;
        pp[(size_t)hq * (SEQ / 2) * 4 + ((t0 >> 1) + p) * 4 + i] = s;
    }
}

// ---------------------------------------------------------------------------
// Merged kernel, 256 blocks (ONE wave): [0,128) scan, [128,256) gate GEMM.
// Scan: 2-step recurrence + precomputed pair scalars.
// Smem/buf (floats): q 4096 | k 4096 | v 512 | b 32 | a 32 | pp 64 = 8832
// ---------------------------------------------------------------------------
#define TSCHUNK 32
#define SC_K   4096
#define SC_V   8192
#define SC_B   8704
#define SC_A   8736
#define SC_P   8768
#define SCAN_BUF_F 8832

__global__ void __launch_bounds__(256, 2) scan_gate_kernel(
    const float* __restrict__ qkv, const float* __restrict__ beta,
    const float* __restrict__ alpha, const float* __restrict__ pp,
    float* __restrict__ ctx,
    const __nv_bfloat16* __restrict__ x_hi, const __nv_bfloat16* __restrict__ x_lo,
    const __nv_bfloat16* __restrict__ wg_hi, const __nv_bfloat16* __restrict__ wg_lo,
    float* __restrict__ gate)
{
    extern __shared__ char dynsmem[];
    const int bx  = blockIdx.x;
    const int tid = threadIdx.x;

    if (bx >= 128) {
        const int bi = bx - 128;
        const int bn = (bi & 15) * 128;
        const int bm = (bi >> 4) * 128;
        gemm_tile(dynsmem, tid, bm, bn, x_hi, x_lo, wg_hi, wg_lo,
                  gate, DOVG, 1, (const float*)0, (const float*)0,
                  (float*)0, (float*)0);
        return;
    }

    // ---- scan ----
    float* ss = (float*)dynsmem;
    const int h  = bx >> 3;
    const int cb = bx & 7;
    const int hq = h >> 1;
    const int j   = tid >> 4;
    const int sub = tid & 15;

    const uint32_t ssb = smem_u32(ss);

    const float* qbase = qkv + hq * 128;
    const float* kbase = qkv + 1024 + hq * 128;
    const float* vbase = qkv + 2048 + h * 128 + cb * 16;
    const float* bbase = beta + h * SEQ;
    const float* abase = alpha + h * SEQ;
    const float* pbase = pp + (size_t)hq * (SEQ / 2) * 4;
    float* obase = ctx + h * 128 + cb * 16 + j;

    const int c0 = sub * 2;
    const int c0s = c0 ^ (c0 >> 3);
    const int c1 = c0 + 1;
    const int c1s = c1 ^ (c1 >> 3);

#define SCAN_ISSUE(buf, t0)                                                    \
    do {                                                                       \
        uint32_t sbb = ssb + (uint32_t)(buf) * (SCAN_BUF_F * 4);               \
        _Pragma("unroll")                                                      \
        for (int u = 0; u < 4; ++u) {                                          \
            int lin = tid + u * 256;                                           \
            int tt = lin >> 5, d4 = lin & 31;                                  \
            int sw = d4 ^ (d4 >> 3);                                           \
            size_t goff = (size_t)((t0) + tt) * FUSEDC + d4 * 4;               \
            uint32_t so = (uint32_t)(tt * 32 + sw) * 16;                       \
            cp_async16(sbb + so, qbase + goff);                                \
            cp_async16(sbb + SC_K * 4 + so, kbase + goff);                     \
        }                                                                      \
        if (tid < 128) {                                                       \
            int tt = tid >> 2, j4 = tid & 3;                                   \
            cp_async16(sbb + SC_V * 4 + (uint32_t)tid * 16,                    \
                       vbase + (size_t)((t0) + tt) * FUSEDC + j4 * 4);         \
        } else if (tid < 160) {                                                \
            cp_async4(sbb + SC_B * 4 + (uint32_t)(tid - 128) * 4,              \
                      bbase + (t0) + tid - 128);                               \
        } else if (tid < 192) {                                                \
            cp_async4(sbb + SC_A * 4 + (uint32_t)(tid - 160) * 4,              \
                      abase + (t0) + tid - 160);                               \
        } else if (tid < 208) {                                                \
            cp_async16(sbb + SC_P * 4 + (uint32_t)(tid - 192) * 16,            \
                       pbase + ((t0) >> 1) * 4 + (tid - 192) * 4);             \
        }                                                                      \
        cp_commit();                                                           \
    } while (0)

    float S[8];
#pragma unroll
    for (int i = 0; i < 8; ++i) S[i] = 0.f;

    SCAN_ISSUE(0, 0);

    for (int ci = 0; ci < SEQ / TSCHUNK; ++ci) {
        asm volatile("cp.async.wait_group 0;");
        __syncthreads();
        if (ci + 1 < SEQ / TSCHUNK) SCAN_ISSUE((ci + 1) & 1, (ci + 1) * TSCHUNK);

        const float* sqf = ss + (ci & 1) * SCAN_BUF_F;
        const float* skf = sqf + SC_K;
        const float* svf = sqf + SC_V;
        const float* sbf = sqf + SC_B;
        const float* saf = sqf + SC_A;
        const float* spf = sqf + SC_P;
        const int t0 = ci * TSCHUNK;

#pragma unroll 2
        for (int tt = 0; tt < TSCHUNK; tt += 2) {
            float a0 = saf[tt],     b0 = sbf[tt];
            float a1 = saf[tt + 1], b1 = sbf[tt + 1];
            float v0 = svf[tt * 16 + j];
            float v1 = svf[(tt + 1) * 16 + j];
            const int tp = tt >> 1;
            float ckk   = spf[tp * 4 + 0];
            float cqk   = spf[tp * 4 + 1];
            float cq1k  = spf[tp * 4 + 2];
            float cq1k1 = spf[tp * 4 + 3];

            float kr0[8], qr0[8], kr1[8], qr1[8];
            *(float4*)(kr0)     = *(const float4*)&skf[tt * 128 + c0s * 4];
            *(float4*)(kr0 + 4) = *(const float4*)&skf[tt * 128 + c1s * 4];
            *(float4*)(qr0)     = *(const float4*)&sqf[tt * 128 + c0s * 4];
            *(float4*)(qr0 + 4) = *(const float4*)&sqf[tt * 128 + c1s * 4];
            *(float4*)(kr1)     = *(const float4*)&skf[(tt + 1) * 128 + c0s * 4];
            *(float4*)(kr1 + 4) = *(const float4*)&skf[(tt + 1) * 128 + c1s * 4];
            *(float4*)(qr1)     = *(const float4*)&sqf[(tt + 1) * 128 + c0s * 4];
            *(float4*)(qr1 + 4) = *(const float4*)&sqf[(tt + 1) * 128 + c1s * 4];

            float p = 0.f, r = 0.f, s = 0.f, w = 0.f;
#pragma unroll
            for (int i = 0; i < 8; ++i) {
                p = fmaf(kr0[i], S[i], p);
                r = fmaf(kr1[i], S[i], r);
                s = fmaf(qr0[i], S[i], s);
                w = fmaf(qr1[i], S[i], w);
            }
#pragma unroll
            for (int m = 1; m <= 8; m <<= 1) {
                p += __shfl_xor_sync(0xffffffffu, p, m);
                r += __shfl_xor_sync(0xffffffffu, r, m);
                s += __shfl_xor_sync(0xffffffffu, s, m);
                w += __shfl_xor_sync(0xffffffffu, w, m);
            }

            float u0  = b0 * fmaf(-a0, p, v0);
            float kv1 = a1 * fmaf(ckk, u0, a0 * r);
            float u1  = b1 * (v1 - kv1);
            float o0  = fmaf(cqk, u0, a0 * s);
            float aa  = a1 * a0;
            float o1  = fmaf(cq1k1, u1, fmaf(a1 * cq1k, u0, aa * w));
            float c0u = a1 * u0;

#pragma unroll
            for (int i = 0; i < 8; ++i)
                S[i] = fmaf(aa, S[i], fmaf(c0u, kr0[i], u1 * kr1[i]));

            if (sub == 0) {
                obase[(size_t)(t0 + tt) * DOVG]     = o0;
                obase[(size_t)(t0 + tt + 1) * DOVG] = o1;
            }
        }
        __syncthreads();
    }
#undef SCAN_ISSUE
}

// ---------------------------------------------------------------------------
// one-shot fp32 -> (bf16 hi, lo) split over all operands (incl. w_out)
// ---------------------------------------------------------------------------
#define N4_X   (SEQ * DIN / 4)
#define N4_QKV (FUSEDC * DIN / 4)
#define N4_WG  (DOVG * DIN / 4)
#define N4_WO  (DOVG * DIN / 4)
#define N4_WB  (16 * DIN / 4)
#define N4_WA  (16 * DIN / 4)
#define N4_TOT (N4_X + N4_QKV + N4_WG + N4_WO + N4_WB + N4_WA)
#define N8_TOT (N4_TOT / 2)

__global__ void __launch_bounds__(256) split_all(
    const float* __restrict__ x, const float* __restrict__ wqkv,
    const float* __restrict__ wg, const float* __restrict__ wo,
    const float* __restrict__ wb, const float* __restrict__ wa,
    __nv_bfloat16* xh, __nv_bfloat16* xl,
    __nv_bfloat16* qh, __nv_bfloat16* ql,
    __nv_bfloat16* gh, __nv_bfloat16* gl,
    __nv_bfloat16* oh, __nv_bfloat16* ol,
    __nv_bfloat16* bah, __nv_bfloat16* bal)
{
    int g = blockIdx.x * 256 + threadIdx.x;
    if (g >= N8_TOT) return;
    int i = g * 2;
    const float* src;
    __nv_bfloat16 *hi, *lo;
    if (i < N4_X) { src = x; hi = xh; lo = xl; }
    else if ((i -= N4_X) < N4_QKV) { src = wqkv; hi = qh; lo = ql; }
    else if ((i -= N4_QKV) < N4_WG) { src = wg; hi = gh; lo = gl; }
    else if ((i -= N4_WG) < N4_WO) { src = wo; hi = oh; lo = ol; }
    else if ((i -= N4_WO) < N4_WB) { src = wb; hi = bah; lo = bal; }
    else { i -= N4_WB; src = wa; hi = bah + 16 * DIN; lo = bal + 16 * DIN; }

    float4 v0 = ((const float4*)src)[i];
    float4 v1 = ((const float4*)src)[i + 1];
    uint4 H, L;
    H.x = split_pair(v0.x, v0.y, L.x);
    H.y = split_pair(v0.z, v0.w, L.y);
    H.z = split_pair(v1.x, v1.y, L.z);
    H.w = split_pair(v1.z, v1.w, L.w);
    ((uint4*)hi)[i >> 1] = H;
    ((uint4*)lo)[i >> 1] = L;
}

// ---------------------------------------------------------------------------
// rms_norm(ctx) * rms_w * gate -> split bf16 (hi/lo); 2 heads per CTA
// grid (SEQ, HV/2), 256 threads
// ---------------------------------------------------------------------------
__global__ void __launch_bounds__(256) rms_gate_kernel(
    const float* __restrict__ ctx, const float* __restrict__ gate,
    const float* __restrict__ rms_w,
    __nv_bfloat16* __restrict__ ghi, __nv_bfloat16* __restrict__ glo)
{
    const int t = blockIdx.x;
    const int hh = threadIdx.x >> 7;                     // head within CTA
    const int h = blockIdx.y * 2 + hh;
    const int tid = threadIdx.x & 127;
    const int wrp = (threadIdx.x >> 5) & 3;
    size_t idx = (size_t)t * DOVG + h * 128 + tid;
    float v = ctx[idx];
    float ss = v * v;
#pragma unroll
    for (int m = 16; m; m >>= 1) ss += __shfl_xor_sync(0xffffffffu, ss, m);
    __shared__ float sw[2][4];
    if ((threadIdx.x & 31) == 0) sw[hh][wrp] = ss;
    __syncthreads();
    float tot = sw[hh][0] + sw[hh][1] + sw[hh][2] + sw[hh][3];
    float sc = rsqrtf(tot * (1.f / 128.f) + 1e-6f);
    float r = v * sc * rms_w[tid] * gate[idx];
    __nv_bfloat16 hbf = __float2bfloat16(r);
    ghi[idx] = hbf;
    glo[idx] = __float2bfloat16(r - __bfloat162float(hbf));
}

// ---------------------------------------------------------------------------
extern "C" void kernel_launch(void* const* d_in, const int* in_sizes, int n_in,
                              void* d_out, int out_size)
{
    const float* x       = (const float*)d_in[0];
    const float* w_qkv   = (const float*)d_in[1];
    const float* w_gate  = (const float*)d_in[2];
    const float* w_beta  = (const float*)d_in[3];
    const float* w_alpha = (const float*)d_in[4];
    const float* log_A   = (const float*)d_in[5];
    const float* dt_bias = (const float*)d_in[6];
    const float* conv_w  = (const float*)d_in[7];
    const float* rms_w   = (const float*)d_in[8];
    const float* w_out   = (const float*)d_in[9];
    float* out = (float*)d_out;

    float *qkv_pre, *qkv, *gate, *ctx, *beta, *alpha, *pp;
    __nv_bfloat16 *x_hi, *x_lo, *wqkv_hi, *wqkv_lo, *wg_hi, *wg_lo,
                  *wo_hi, *wo_lo, *gctx_hi, *gctx_lo, *wba_hi, *wba_lo;
    cudaGetSymbolAddress((void**)&qkv_pre, g_qkv_pre);
    cudaGetSymbolAddress((void**)&qkv,     g_qkv);
    cudaGetSymbolAddress((void**)&gate,    g_gate);
    cudaGetSymbolAddress((void**)&ctx,     g_ctx);
    cudaGetSymbolAddress((void**)&beta,    g_beta);
    cudaGetSymbolAddress((void**)&alpha,   g_alpha);
    cudaGetSymbolAddress((void**)&pp,      g_pp);
    cudaGetSymbolAddress((void**)&x_hi,    g_x_hi);
    cudaGetSymbolAddress((void**)&x_lo,    g_x_lo);
    cudaGetSymbolAddress((void**)&wqkv_hi, g_wqkv_hi);
    cudaGetSymbolAddress((void**)&wqkv_lo, g_wqkv_lo);
    cudaGetSymbolAddress((void**)&wg_hi,   g_wg_hi);
    cudaGetSymbolAddress((void**)&wg_lo,   g_wg_lo);
    cudaGetSymbolAddress((void**)&wo_hi,   g_wo_hi);
    cudaGetSymbolAddress((void**)&wo_lo,   g_wo_lo);
    cudaGetSymbolAddress((void**)&gctx_hi, g_gctx_hi);
    cudaGetSymbolAddress((void**)&gctx_lo, g_gctx_lo);
    cudaGetSymbolAddress((void**)&wba_hi,  g_wba_hi);
    cudaGetSymbolAddress((void**)&wba_lo,  g_wba_lo);

    cudaFuncSetAttribute(gemm3c, cudaFuncAttributeMaxDynamicSharedMemorySize, GSMEM);
    cudaFuncSetAttribute(scan_gate_kernel, cudaFuncAttributeMaxDynamicSharedMemorySize, GSMEM);

    // 0) one-shot precision splits
    split_all<<<(N8_TOT + 255) / 256, 256>>>(
        x, w_qkv, w_gate, w_out, w_beta, w_alpha,
        x_hi, x_lo, wqkv_hi, wqkv_lo, wg_hi, wg_lo, wo_hi, wo_lo, wba_hi, wba_lo);

    // 1) qkv + beta/alpha projections (gate deferred to the scan window)
    gemm3c<<<dim3((FUSEDC + 128) / 128, SEQ / 128), 256, GSMEM>>>(
        x_hi, x_lo,
        wqkv_hi, wqkv_lo, qkv_pre, FUSEDC, 0,
        wba_hi, wba_lo,
        log_A, dt_bias, beta, alpha);

    // 2) conv+silu (+l2norm +pair scalars for q/k) — one launch
    conv_all_kernel<<<dim3(SEQ / 4, 16), 256>>>(qkv_pre, conv_w, qkv, pp);

    // 3) gated delta-rule scan (2-step, pair scalars) + gate GEMM — ONE wave
    scan_gate_kernel<<<256, 256, GSMEM>>>(qkv, beta, alpha, pp, ctx,
                                          x_hi, x_lo, wg_hi, wg_lo, gate);

    // 4) rms norm * gate -> split bf16 (2 heads per CTA)
    rms_gate_kernel<<<dim3(SEQ, HV / 2), 256>>>(ctx, gate, rms_w, gctx_hi, gctx_lo);

    // 5) output projection
    gemm3c<<<dim3(DOVG / 128, SEQ / 128), 256, GSMEM>>>(
        gctx_hi, gctx_lo,
        wo_hi, wo_lo, out, DOVG, 0,
        wba_hi, wba_lo,
        log_A, dt_bias, (float*)0, (float*)0);
}